// round 13
// baseline (speedup 1.0000x reference)
#include <cuda_runtime.h>
#include <cuda_fp16.h>

// FastFood layer, D=1024, R=4, M=16384 rows. One warp per row. Zero shuffles.
// R12 structure + TWO-CHOICE gather image:
//   copy A: 17-word rows (word = 17*row + k/2), copy B: 19-word rows at word 544.
//   Both odd strides -> CF row writes. bankB-bankA = 2*row mod 32 (decorrelated).
//   prep greedily assigns each permutation element to the copy that minimizes
//   per-gather-instruction bank conflicts; choice is baked into the PG slot.
// Layouts: A: idx = k*32 + l   B: idx = l*32 + k.

#define FF_D 1024
#define FF_R 4
#define WPB 8
#define THREADS (WPB * 32)
#define RSH 34           // halves per copy-A row (17 words)
#define BWORD 544        // copy-B word base (= 32*17)
#define BHALF 1088       // copy-B half base
#define IMGW 1152        // total words per warp image (32*17 + 32*19)

typedef unsigned long long u64;
typedef unsigned int u32;

__device__ u32  g_bpack[FF_R * 32];   // bit k = signbit(B[r][k*32+l])
__device__ int4 g_pg4[FF_R * 256];    // [r][q*32+l]: entries for j = l*32+4q+{0..3}
__device__ u32  g_sh2[FF_R * 512];    // [r][p*32+l] = half2(S'[2p*32+l], S'[(2p+1)*32+l])

__global__ void prep_kernel(const float* __restrict__ B, const float* __restrict__ G,
                            const float* __restrict__ S, const int* __restrict__ P) {
    int t = blockIdx.x * blockDim.x + threadIdx.x;
    int stride = gridDim.x * blockDim.x;
    if (t < FF_R * 32) {
        int r = t >> 5, l = t & 31;
        u32 m = 0;
        #pragma unroll
        for (int k = 0; k < 32; k++)
            m |= (__float_as_uint(B[r * FF_D + k * 32 + l]) >> 31) << k;
        g_bpack[t] = m;
    }
    // PG with greedy two-choice bank assignment. Thread (r, s) handles gather
    // instruction slot s (k' = s): lanes u read element P[r][u*32+s].
    if (t < FF_R * 32) {
        int r = t >> 5, s = t & 31;
        u32* pg = reinterpret_cast<u32*>(g_pg4) + r * 1024 + (s >> 2) * 128 + (s & 3);
        int cnt[32];
        #pragma unroll
        for (int b = 0; b < 32; b++) cnt[b] = 0;
        for (int u = 0; u < 32; u++) {
            int i = P[r * FF_D + u * 32 + s];
            int row = i >> 5, half = i & 31, word = half >> 1;
            int bA = (17 * row + word) & 31;
            int bB = (19 * row + word) & 31;
            u32 slot;
            if (cnt[bB] < cnt[bA]) { cnt[bB]++; slot = (u32)(BHALF + row * 38 + half); }
            else                   { cnt[bA]++; slot = (u32)(row * RSH + half); }
            unsigned short gh = __half_as_ushort(__float2half_rn(G[r * FF_D + u * 32 + s]));
            pg[u * 4] = (slot << 16) | (u32)gh;
        }
    }
    for (int i = t; i < FF_R * 512; i += stride) {
        int r = i >> 9, rem = i & 511;
        int p = rem >> 5, l = rem & 31;
        float s0 = S[r * FF_D + (2 * p)     * 32 + l] * 0.03125f;
        float s1 = S[r * FF_D + (2 * p + 1) * 32 + l] * 0.03125f;
        __half2 h = __floats2half2_rn(s0, s1);
        g_sh2[i] = *reinterpret_cast<u32*>(&h);
    }
}

// ---- f32x2 helpers ----
__device__ __forceinline__ u64 pk(float a, float b) {
    u64 u; asm("mov.b64 %0, {%1,%2};" : "=l"(u) : "f"(a), "f"(b)); return u;
}
__device__ __forceinline__ float2 up(u64 u) {
    float2 r; asm("mov.b64 {%0,%1}, %2;" : "=f"(r.x), "=f"(r.y) : "l"(u)); return r;
}
__device__ __forceinline__ u64 swp(u64 v) {
    u64 r;
    asm("{\n\t.reg .b32 a,b;\n\tmov.b64 {a,b}, %1;\n\tmov.b64 %0, {b,a};\n\t}"
        : "=l"(r) : "l"(v));
    return r;
}
__device__ __forceinline__ u64 addx2(u64 a, u64 b) {
    u64 r; asm("add.rn.f32x2 %0, %1, %2;" : "=l"(r) : "l"(a), "l"(b)); return r;
}
__device__ __forceinline__ u64 fmax2(u64 a, u64 b, u64 c) {   // a*b + c
    u64 r; asm("fma.rn.f32x2 %0, %1, %2, %3;" : "=l"(r) : "l"(a), "l"(b), "l"(c)); return r;
}
__device__ __forceinline__ u64 mulx2(u64 a, u64 b) {
    u64 r; asm("mul.rn.f32x2 %0, %1, %2;" : "=l"(r) : "l"(a), "l"(b)); return r;
}
#define C_P1M1 0xBF8000003F800000ULL   // {+1.0, -1.0}
#define C_M1M1 0xBF800000BF800000ULL   // {-1.0, -1.0}

__device__ __forceinline__ u32 h2pack(u64 v) {
    float2 f = up(v);
    __half2 h = __floats2half2_rn(f.x, f.y);
    return *reinterpret_cast<u32*>(&h);
}
__device__ __forceinline__ float2 h2unpack(u32 w) {
    __half2 h = *reinterpret_cast<__half2*>(&w);
    return __half22float2(h);
}

// H32 over {half-bit of each pair} + {4 register-pair index bits}
__device__ __forceinline__ void fwht2x(u64 va[16]) {
    #pragma unroll
    for (int p = 0; p < 16; p++)
        va[p] = fmax2(va[p], C_P1M1, swp(va[p]));
    #pragma unroll
    for (int m = 1; m <= 8; m <<= 1) {
        #pragma unroll
        for (int p = 0; p < 16; p++) {
            if ((p & m) == 0) {
                u64 a = va[p], b = va[p | m];
                va[p]     = addx2(a, b);
                va[p | m] = fmax2(b, C_M1M1, a);
            }
        }
    }
}

__global__ __launch_bounds__(THREADS, 4)
void fastfood_kernel(const float* __restrict__ x,
                     float* __restrict__ out, int M)
{
    __shared__ u32 sc[WPB][IMGW];                  // 4608 B per warp image
    const int warp = threadIdx.x >> 5;
    const int t    = threadIdx.x & 31;             // lane
    const int row  = blockIdx.x * WPB + warp;
    if (row >= M) return;
    u32*    sm32 = sc[warp];
    __half* smh  = reinterpret_cast<__half*>(sm32);
    const float* xr = x + (size_t)row * FF_D;

    #pragma unroll 1
    for (int r = 0; r < FF_R; r++) {
        // ---- v = x * B[r] (sign-bit xor), layout A: va[p] = (k=2p, k=2p+1) ----
        const u32 bp = g_bpack[r * 32 + t];
        u64 va[16];
        #pragma unroll
        for (int p = 0; p < 16; p++) {
            u32 m0 = (bp << (31 - 2 * p))     & 0x80000000u;
            u32 m1 = (bp << (31 - 2 * p - 1)) & 0x80000000u;
            float lo = __uint_as_float(__float_as_uint(__ldg(&xr[(2 * p)     * 32 + t])) ^ m0);
            float hi = __uint_as_float(__float_as_uint(__ldg(&xr[(2 * p + 1) * 32 + t])) ^ m1);
            va[p] = pk(lo, hi);
        }

        // ---- FWHT #1: high bits (layout A) ----
        fwht2x(va);
        // T1 write: value (k, t) -> copy-A row k, half t. CF (pair-merge).
        #pragma unroll
        for (int p = 0; p < 16; p++) {
            float2 f = up(va[p]);
            smh[(2 * p)     * RSH + t] = __float2half_rn(f.x);
            smh[(2 * p + 1) * RSH + t] = __float2half_rn(f.y);
        }
        __syncwarp();
        // T1 read: own copy-A row. CF (17 invertible mod 32).
        #pragma unroll
        for (int w = 0; w < 16; w++) {
            float2 f = h2unpack(sm32[t * 17 + w]);
            va[w] = pk(f.x, f.y);
        }
        // ---- FWHT #1: low bits (layout B) -> h1 ----
        fwht2x(va);

        // ---- gather image: write BOTH copies (own rows, both CF) ----
        #pragma unroll
        for (int w = 0; w < 16; w++) {
            u32 c = h2pack(va[w]);
            sm32[t * 17 + w]         = c;          // copy A (17-word rows)
            sm32[BWORD + t * 19 + w] = c;          // copy B (19-word rows)
        }
        __syncwarp();
        // ---- permuted gather * G (slot chosen per element by prep greedy) ----
        const int4* PG = g_pg4 + r * 256;
        #pragma unroll
        for (int q = 0; q < 8; q++) {
            int4 pg = __ldg(&PG[q * 32 + t]);
            u32 e0 = (u32)pg.x, e1 = (u32)pg.y, e2 = (u32)pg.z, e3 = (u32)pg.w;
            float t0 = __half2float(smh[e0 >> 16]);
            float t1 = __half2float(smh[e1 >> 16]);
            float t2 = __half2float(smh[e2 >> 16]);
            float t3 = __half2float(smh[e3 >> 16]);
            float g0 = __half2float(__ushort_as_half((unsigned short)(e0 & 0xffffu)));
            float g1 = __half2float(__ushort_as_half((unsigned short)(e1 & 0xffffu)));
            float g2 = __half2float(__ushort_as_half((unsigned short)(e2 & 0xffffu)));
            float g3 = __half2float(__ushort_as_half((unsigned short)(e3 & 0xffffu)));
            va[2 * q]     = mulx2(pk(t0, t1), pk(g0, g1));
            va[2 * q + 1] = mulx2(pk(t2, t3), pk(g2, g3));
        }
        __syncwarp();                                   // all gathers done before overwrite

        // ---- FWHT #2: low bits (layout B) ----
        fwht2x(va);
        // T2 write: own copy-A row. CF.
        #pragma unroll
        for (int w = 0; w < 16; w++)
            sm32[t * 17 + w] = h2pack(va[w]);
        __syncwarp();
        // T2 read: column side, value j = k*32 + t from copy-A row k half t. CF.
        #pragma unroll
        for (int p = 0; p < 16; p++) {
            float f0 = __half2float(smh[(2 * p)     * RSH + t]);
            float f1 = __half2float(smh[(2 * p + 1) * RSH + t]);
            va[p] = pk(f0, f1);
        }
        // ---- FWHT #2: high bits (layout A) ----
        fwht2x(va);

        // ---- scale (half2-paired prescaled S) + coalesced store ----
        const u32* Sh = g_sh2 + r * 512;
        float* o = out + (size_t)row * (FF_R * FF_D) + r * FF_D;
        #pragma unroll
        for (int p = 0; p < 16; p++) {
            float2 s = h2unpack(__ldg(&Sh[p * 32 + t]));
            float2 f = up(mulx2(va[p], pk(s.x, s.y)));
            o[(2 * p)     * 32 + t] = f.x;
            o[(2 * p + 1) * 32 + t] = f.y;
        }
    }
}

extern "C" void kernel_launch(void* const* d_in, const int* in_sizes, int n_in,
                              void* d_out, int out_size) {
    const float* x = (const float*)d_in[0];   // (4,512,8,1024) fp32
    const float* B = (const float*)d_in[1];   // (4,1024) fp32
    const float* G = (const float*)d_in[2];   // (4,1024) fp32
    const float* S = (const float*)d_in[3];   // (4,1024) fp32
    const int*   P = (const int*)  d_in[4];   // (4,1024) int32
    float* out = (float*)d_out;

    const int M = in_sizes[0] / FF_D;         // 16384 rows
    prep_kernel<<<32, 256>>>(B, G, S, P);
    const int blocks = (M + WPB - 1) / WPB;
    fastfood_kernel<<<blocks, THREADS>>>(x, out, M);
}

// round 14
// speedup vs baseline: 1.2260x; 1.2260x over previous
#include <cuda_runtime.h>
#include <cuda_fp16.h>

// FastFood layer, D=1024, R=4, M=16384 rows. One warp per row. Zero shuffles.
// R12 structure (fp16 transpose image, CF 17-word rows, f32x2 butterflies) plus:
//   x cached ONCE per row in a private fp16 word-paired smem region, so the
//   per-r input phase is 16 CF LDS.32 instead of 32 LDG.32.
// Layouts: A: idx = k*32 + l   B: idx = l*32 + k  (k = reg-pair halves, l = lane)
// Transpose image: 32 rows x 17 words. half-slot(i) = (i>>5)*34 + (i&31).
// x image at word offset 544: word(p, t) = half2(x[2p*32+t], x[(2p+1)*32+t]).

#define FF_D 1024
#define FF_R 4
#define WPB 8
#define THREADS (WPB * 32)
#define RSH 34      // halves per transpose-image row
#define RSW 17      // words per transpose-image row
#define XOFF 544    // x-image word base (= 32*17)
#define IMGW 1056   // total words per warp (544 + 512)

typedef unsigned long long u64;
typedef unsigned int u32;

__device__ u32  g_bpack[FF_R * 32];   // bit k = signbit(B[r][k*32+l])
__device__ int4 g_pg4[FF_R * 256];    // [r][q*32+l]: entries for j = l*32+4q+{0..3}
__device__ u32  g_sh2[FF_R * 512];    // [r][p*32+l] = half2(S'[2p*32+l], S'[(2p+1)*32+l])

__global__ void prep_kernel(const float* __restrict__ B, const float* __restrict__ G,
                            const float* __restrict__ S, const int* __restrict__ P) {
    int t = blockIdx.x * blockDim.x + threadIdx.x;
    int stride = gridDim.x * blockDim.x;
    if (t < FF_R * 32) {
        int r = t >> 5, l = t & 31;
        u32 m = 0;
        #pragma unroll
        for (int k = 0; k < 32; k++)
            m |= (__float_as_uint(B[r * FF_D + k * 32 + l]) >> 31) << k;
        g_bpack[t] = m;
    }
    for (int i = t; i < FF_R * 256; i += stride) {
        int r = i >> 8, rem = i & 255;
        int q = rem >> 5, l = rem & 31;
        int j = r * FF_D + l * 32 + 4 * q;
        u32 e[4];
        #pragma unroll
        for (int u = 0; u < 4; u++) {
            int p = P[j + u];
            u32 slot = (u32)((p >> 5) * RSH + (p & 31));   // half-slot
            unsigned short gh = __half_as_ushort(__float2half_rn(G[j + u]));
            e[u] = (slot << 16) | (u32)gh;
        }
        g_pg4[i] = make_int4((int)e[0], (int)e[1], (int)e[2], (int)e[3]);
    }
    for (int i = t; i < FF_R * 512; i += stride) {
        int r = i >> 9, rem = i & 511;
        int p = rem >> 5, l = rem & 31;
        float s0 = S[r * FF_D + (2 * p)     * 32 + l] * 0.03125f;
        float s1 = S[r * FF_D + (2 * p + 1) * 32 + l] * 0.03125f;
        __half2 h = __floats2half2_rn(s0, s1);
        g_sh2[i] = *reinterpret_cast<u32*>(&h);
    }
}

// ---- f32x2 helpers ----
__device__ __forceinline__ u64 pk(float a, float b) {
    u64 u; asm("mov.b64 %0, {%1,%2};" : "=l"(u) : "f"(a), "f"(b)); return u;
}
__device__ __forceinline__ float2 up(u64 u) {
    float2 r; asm("mov.b64 {%0,%1}, %2;" : "=f"(r.x), "=f"(r.y) : "l"(u)); return r;
}
__device__ __forceinline__ u64 swp(u64 v) {
    u64 r;
    asm("{\n\t.reg .b32 a,b;\n\tmov.b64 {a,b}, %1;\n\tmov.b64 %0, {b,a};\n\t}"
        : "=l"(r) : "l"(v));
    return r;
}
__device__ __forceinline__ u64 addx2(u64 a, u64 b) {
    u64 r; asm("add.rn.f32x2 %0, %1, %2;" : "=l"(r) : "l"(a), "l"(b)); return r;
}
__device__ __forceinline__ u64 fmax2(u64 a, u64 b, u64 c) {   // a*b + c
    u64 r; asm("fma.rn.f32x2 %0, %1, %2, %3;" : "=l"(r) : "l"(a), "l"(b), "l"(c)); return r;
}
__device__ __forceinline__ u64 mulx2(u64 a, u64 b) {
    u64 r; asm("mul.rn.f32x2 %0, %1, %2;" : "=l"(r) : "l"(a), "l"(b)); return r;
}
#define C_P1M1 0xBF8000003F800000ULL   // {+1.0, -1.0}
#define C_M1M1 0xBF800000BF800000ULL   // {-1.0, -1.0}

__device__ __forceinline__ u32 h2pack(u64 v) {
    float2 f = up(v);
    __half2 h = __floats2half2_rn(f.x, f.y);
    return *reinterpret_cast<u32*>(&h);
}
__device__ __forceinline__ float2 h2unpack(u32 w) {
    __half2 h = *reinterpret_cast<__half2*>(&w);
    return __half22float2(h);
}

// H32 over {half-bit of each pair} + {4 register-pair index bits}
__device__ __forceinline__ void fwht2x(u64 va[16]) {
    #pragma unroll
    for (int p = 0; p < 16; p++)
        va[p] = fmax2(va[p], C_P1M1, swp(va[p]));
    #pragma unroll
    for (int m = 1; m <= 8; m <<= 1) {
        #pragma unroll
        for (int p = 0; p < 16; p++) {
            if ((p & m) == 0) {
                u64 a = va[p], b = va[p | m];
                va[p]     = addx2(a, b);
                va[p | m] = fmax2(b, C_M1M1, a);
            }
        }
    }
}

__global__ __launch_bounds__(THREADS, 4)
void fastfood_kernel(const float* __restrict__ x,
                     float* __restrict__ out, int M)
{
    __shared__ u32 sc[WPB][IMGW];                  // 4224 B per warp
    const int warp = threadIdx.x >> 5;
    const int t    = threadIdx.x & 31;             // lane
    const int row  = blockIdx.x * WPB + warp;
    if (row >= M) return;
    u32*    sm32 = sc[warp];
    __half* smh  = reinterpret_cast<__half*>(sm32);
    u32*    ximg = sm32 + XOFF;
    const float* xr = x + (size_t)row * FF_D;

    // ---- load x once, pack k-pairs to fp16, store to private x-image ----
    // word (p, t) written and later read ONLY by this thread: no syncs needed.
    #pragma unroll
    for (int p = 0; p < 16; p++) {
        float lo = __ldg(&xr[(2 * p)     * 32 + t]);
        float hi = __ldg(&xr[(2 * p + 1) * 32 + t]);
        __half2 h = __floats2half2_rn(lo, hi);
        ximg[p * 32 + t] = *reinterpret_cast<u32*>(&h);
    }

    #pragma unroll 1
    for (int r = 0; r < FF_R; r++) {
        // ---- v = x * B[r] (sign-bit xor on fp16-cached x), layout A ----
        const u32 bp = g_bpack[r * 32 + t];
        u64 va[16];
        #pragma unroll
        for (int p = 0; p < 16; p++) {
            float2 f = h2unpack(ximg[p * 32 + t]);
            u32 m0 = (bp << (31 - 2 * p))     & 0x80000000u;
            u32 m1 = (bp << (31 - 2 * p - 1)) & 0x80000000u;
            va[p] = pk(__uint_as_float(__float_as_uint(f.x) ^ m0),
                       __uint_as_float(__float_as_uint(f.y) ^ m1));
        }

        // ---- FWHT #1: high bits (layout A) ----
        fwht2x(va);
        // T1 write: value (k, t) -> row k, half t. CF (pair-merge).
        // (prev iter's T2 reads used this thread's identical address set: no sync)
        #pragma unroll
        for (int p = 0; p < 16; p++) {
            float2 f = up(va[p]);
            smh[(2 * p)     * RSH + t] = __float2half_rn(f.x);
            smh[(2 * p + 1) * RSH + t] = __float2half_rn(f.y);
        }
        __syncwarp();
        // T1 read: own row t, words w -> halves (k'=2w, 2w+1). CF (17 odd).
        #pragma unroll
        for (int w = 0; w < 16; w++) {
            float2 f = h2unpack(sm32[t * RSW + w]);
            va[w] = pk(f.x, f.y);
        }
        // ---- FWHT #1: low bits (layout B) -> h1 ----
        fwht2x(va);

        // ---- gather image: own-row word writes (only this thread read row t) ----
        #pragma unroll
        for (int w = 0; w < 16; w++)
            sm32[t * RSW + w] = h2pack(va[w]);
        __syncwarp();
        // ---- permuted gather * G: thread t <- j = t*32 + 4q + u ----
        const int4* PG = g_pg4 + r * 256;
        #pragma unroll
        for (int q = 0; q < 8; q++) {
            int4 pg = __ldg(&PG[q * 32 + t]);
            u32 e0 = (u32)pg.x, e1 = (u32)pg.y, e2 = (u32)pg.z, e3 = (u32)pg.w;
            float t0 = __half2float(smh[e0 >> 16]);
            float t1 = __half2float(smh[e1 >> 16]);
            float t2 = __half2float(smh[e2 >> 16]);
            float t3 = __half2float(smh[e3 >> 16]);
            float g0 = __half2float(__ushort_as_half((unsigned short)(e0 & 0xffffu)));
            float g1 = __half2float(__ushort_as_half((unsigned short)(e1 & 0xffffu)));
            float g2 = __half2float(__ushort_as_half((unsigned short)(e2 & 0xffffu)));
            float g3 = __half2float(__ushort_as_half((unsigned short)(e3 & 0xffffu)));
            va[2 * q]     = mulx2(pk(t0, t1), pk(g0, g1));
            va[2 * q + 1] = mulx2(pk(t2, t3), pk(g2, g3));
        }
        __syncwarp();                                   // all gathers done before overwrite

        // ---- FWHT #2: low bits (layout B) ----
        fwht2x(va);
        // T2 write: own-row word writes. CF.
        #pragma unroll
        for (int w = 0; w < 16; w++)
            sm32[t * RSW + w] = h2pack(va[w]);
        __syncwarp();
        // T2 read: column side, value j = k*32 + t from row k half t. CF (pair-merge).
        #pragma unroll
        for (int p = 0; p < 16; p++) {
            float f0 = __half2float(smh[(2 * p)     * RSH + t]);
            float f1 = __half2float(smh[(2 * p + 1) * RSH + t]);
            va[p] = pk(f0, f1);
        }
        // ---- FWHT #2: high bits (layout A) ----
        fwht2x(va);

        // ---- scale (half2-paired prescaled S) + coalesced store ----
        const u32* Sh = g_sh2 + r * 512;
        float* o = out + (size_t)row * (FF_R * FF_D) + r * FF_D;
        #pragma unroll
        for (int p = 0; p < 16; p++) {
            float2 s = h2unpack(__ldg(&Sh[p * 32 + t]));
            float2 f = up(mulx2(va[p], pk(s.x, s.y)));
            o[(2 * p)     * 32 + t] = f.x;
            o[(2 * p + 1) * 32 + t] = f.y;
        }
    }
}

extern "C" void kernel_launch(void* const* d_in, const int* in_sizes, int n_in,
                              void* d_out, int out_size) {
    const float* x = (const float*)d_in[0];   // (4,512,8,1024) fp32
    const float* B = (const float*)d_in[1];   // (4,1024) fp32
    const float* G = (const float*)d_in[2];   // (4,1024) fp32
    const float* S = (const float*)d_in[3];   // (4,1024) fp32
    const int*   P = (const int*)  d_in[4];   // (4,1024) int32
    float* out = (float*)d_out;

    const int M = in_sizes[0] / FF_D;         // 16384 rows
    prep_kernel<<<32, 256>>>(B, G, S, P);
    const int blocks = (M + WPB - 1) / WPB;
    fastfood_kernel<<<blocks, THREADS>>>(x, out, M);
}